// round 16
// baseline (speedup 1.0000x reference)
#include <cuda_runtime.h>
#include <cuda_bf16.h>
#include <cuda_fp16.h>
#include <math.h>
#include <stdint.h>

#define NBATCH 32
#define SLEN   2048
#define NIN    128
#define HSZ    256
#define G4     1024
#define NTOK   (NBATCH * SLEN)   // 65536
#define QDIM   16
#define MMEM   64
#define NCHUNK 128               // 2048 steps / 16 per chunk
#define NTILES 128               // xg tiles per chunk (8 M x 16 N)
#define NW0    32                // xg0 worker CTAs
#define NW1    32                // xg1 worker CTAs

// ---------------- static scratch (allocation-free) ----------------
__device__ float g_xg0[(size_t)NTOK * G4];  // permuted xg, layer 0
__device__ float g_xg1[(size_t)NTOK * G4];  // permuted xg, layer 1
__device__ float g_h  [(size_t)NTOK * HSZ]; // h1 (layer-0 output)
__device__ float g_h2 [(size_t)NTOK * HSZ]; // lstm_out (layer-1 output)
__device__ float g_mv[MMEM * HSZ];          // mem_vals @ Wq^T
__device__ float g_w [NTOK * 4];            // per-token scaled top3 weights
__device__ int   g_idx[NTOK * 4];           // per-token top3 indices
// permuted W_hh split: w1 = fp16(w), w2s = fp16((w - w1) * 2^11)
__device__ __half g_W1_0[G4 * HSZ];
__device__ __half g_W2_0[G4 * HSZ];
__device__ __half g_W1_1[G4 * HSZ];
__device__ __half g_W2_1[G4 * HSZ];
__device__ float g_Wp_ih0[G4 * NIN];
__device__ float g_Wp_ih1[G4 * HSZ];
__device__ float g_bp0[G4];
__device__ float g_bp1[G4];
// h stage: [role 2][cid 2][mat 2][parity 2][2048 u32 words]
__device__ float g_hstage[4 * 8192];
// pipeline sync
__device__ int g_cnt_xg0[NCHUNK];
__device__ int g_cnt_xg1[NCHUNK];
__device__ int g_wm_h1[16];

// =================================================================
// sync helpers
// =================================================================
__device__ __forceinline__ int ld_acq(const int* p) {
    int v;
    asm volatile("ld.acquire.gpu.u32 %0, [%1];" : "=r"(v) : "l"(p) : "memory");
    return v;
}
__device__ __forceinline__ void st_rel(int* p, int v) {
    asm volatile("st.release.gpu.u32 [%0], %1;" :: "l"(p), "r"(v) : "memory");
}
__device__ __forceinline__ void cluster_sync_all() {
    asm volatile("barrier.cluster.arrive.aligned;" ::: "memory");
    asm volatile("barrier.cluster.wait.aligned;" ::: "memory");
}
__device__ __forceinline__ void mma_f16(float* d, const uint4& a,
                                        unsigned b0, unsigned b1) {
    asm volatile(
        "mma.sync.aligned.m16n8k16.row.col.f32.f16.f16.f32 "
        "{%0,%1,%2,%3},{%4,%5,%6,%7},{%8,%9},{%0,%1,%2,%3};"
        : "+f"(d[0]), "+f"(d[1]), "+f"(d[2]), "+f"(d[3])
        : "r"(a.x), "r"(a.y), "r"(a.z), "r"(a.w), "r"(b0), "r"(b1));
}
__device__ __forceinline__ void st16cg(void* p, unsigned short v) {
    asm volatile("st.global.cg.b16 [%0], %1;" :: "l"(p), "h"(v) : "memory");
}
// MUFU-based gates: sigmoid abs err ~2e-7, tanh abs err ~3e-7
__device__ __forceinline__ float fast_sigmoid(float x) {
    return __fdividef(1.f, 1.f + __expf(-x));
}
__device__ __forceinline__ float fast_tanh(float x) {
    return fmaf(-2.f, __fdividef(1.f, 1.f + __expf(2.f * x)), 1.f);
}

// =================================================================
// zero pipeline sync state (run at start of every launch / replay)
// =================================================================
__global__ void zero_sync_kernel() {
    int i = threadIdx.x;
    if (i < NCHUNK) { g_cnt_xg0[i] = 0; g_cnt_xg1[i] = 0; }
    if (i < 16)     g_wm_h1[i] = 0;
}

// =================================================================
// Weight/bias permutation + fp16 hi/scaled-lo split for W_hh
// =================================================================
__global__ void prep_kernel(const float* __restrict__ Whh0,
                            const float* __restrict__ Whh1,
                            const float* __restrict__ Wih0,
                            const float* __restrict__ Wih1,
                            const float* __restrict__ bih0,
                            const float* __restrict__ bhh0,
                            const float* __restrict__ bih1,
                            const float* __restrict__ bhh1)
{
    int p = blockIdx.x;                   // permuted row 0..1023
    int src = (p & 3) * HSZ + (p >> 2);   // gate = p&3, hcol = p>>2
    int tid = threadIdx.x;
    for (int k = tid; k < HSZ; k += blockDim.x) {
        float v0 = Whh0[src * HSZ + k];
        __half a0 = __float2half_rn(v0);
        g_W1_0[p * HSZ + k] = a0;
        g_W2_0[p * HSZ + k] = __float2half_rn((v0 - __half2float(a0)) * 2048.f);
        float v1 = Whh1[src * HSZ + k];
        __half a1 = __float2half_rn(v1);
        g_W1_1[p * HSZ + k] = a1;
        g_W2_1[p * HSZ + k] = __float2half_rn((v1 - __half2float(a1)) * 2048.f);
        g_Wp_ih1[p * HSZ + k] = Wih1[src * HSZ + k];
    }
    for (int k = tid; k < NIN; k += blockDim.x)
        g_Wp_ih0[p * NIN + k] = Wih0[src * NIN + k];
    if (tid == 0) {
        g_bp0[p] = bih0[src] + bhh0[src];
        g_bp1[p] = bih1[src] + bhh1[src];
    }
}

// =================================================================
// MV[m][h] = sum_h' mem_vals[m][h'] * W_out[h][256 + h']
// =================================================================
__global__ void mv_kernel(const float* __restrict__ vals,
                          const float* __restrict__ Wout,
                          float* __restrict__ mv)
{
    int m = blockIdx.x, h = threadIdx.x;
    const float* vrow = vals + (size_t)m * HSZ;
    const float* wrow = Wout + (size_t)h * 2 * HSZ + HSZ;
    float acc = 0.f;
#pragma unroll 8
    for (int k = 0; k < HSZ; k++) acc = fmaf(vrow[k], wrow[k], acc);
    mv[(size_t)m * HSZ + h] = acc;
}

// =================================================================
// Worker GEMM tile: one 64x64 tile of a 16-token xg chunk.
// =================================================================
__device__ void worker_tile(float (*As)[68], float (*Bs)[68],
                            const float* __restrict__ Asrc, int lda,
                            const float* __restrict__ B,
                            const float* __restrict__ bias,
                            float* __restrict__ C,
                            int chunk, int mtile, int ntile)
{
    int tid = threadIdx.x;
    int lr = tid >> 2, lk = (tid & 3) * 4;
    int tx = tid & 15, ty = tid >> 4;
    int mrow = mtile * 64 + lr;
    int b = mrow >> 4, ti = mrow & 15;
    const float* Ap = Asrc + ((size_t)b * SLEN + chunk * 16 + ti) * lda + lk;
    const float* Bp = B + (size_t)(ntile * 64 + lr) * lda + lk;
    float acc[4][4] = {};

    for (int k0 = 0; k0 < lda; k0 += 16) {
        float4 av = *(const float4*)(Ap + k0);
        float4 bv = *(const float4*)(Bp + k0);
        As[lk + 0][lr] = av.x; As[lk + 1][lr] = av.y;
        As[lk + 2][lr] = av.z; As[lk + 3][lr] = av.w;
        Bs[lk + 0][lr] = bv.x; Bs[lk + 1][lr] = bv.y;
        Bs[lk + 2][lr] = bv.z; Bs[lk + 3][lr] = bv.w;
        __syncthreads();
#pragma unroll
        for (int kk = 0; kk < 16; kk++) {
            float4 a4 = *(const float4*)&As[kk][ty * 4];
            float4 b4 = *(const float4*)&Bs[kk][tx * 4];
            float a[4] = {a4.x, a4.y, a4.z, a4.w};
            float bb[4] = {b4.x, b4.y, b4.z, b4.w};
#pragma unroll
            for (int i = 0; i < 4; i++)
#pragma unroll
                for (int j = 0; j < 4; j++)
                    acc[i][j] = fmaf(a[i], bb[j], acc[i][j]);
        }
        __syncthreads();
    }

    int bn = ntile * 64;
    float bcol[4];
#pragma unroll
    for (int j = 0; j < 4; j++) bcol[j] = bias[bn + tx * 4 + j];
#pragma unroll
    for (int i = 0; i < 4; i++) {
        int mr = mtile * 64 + ty * 4 + i;
        int b2 = mr >> 4, t2 = mr & 15;
        size_t row = (size_t)b2 * SLEN + chunk * 16 + t2;
        float4 o;
        o.x = acc[i][0] + bcol[0];
        o.y = acc[i][1] + bcol[1];
        o.z = acc[i][2] + bcol[2];
        o.w = acc[i][3] + bcol[3];
        *(float4*)&C[row * G4 + bn + tx * 4] = o;
    }
}

// =================================================================
// Worker group 0: stream xg0 (no deps, runs ahead freely).
// =================================================================
__device__ void worker0_body(float (*As)[68], float (*Bs)[68],
                             int wkr, const float* __restrict__ x)
{
    int tid = threadIdx.x;
    for (int c = 0; c < NCHUNK; c++) {
        int done = 0;
        for (int tile = wkr; tile < NTILES; tile += NW0) {
            worker_tile(As, Bs, x, NIN, g_Wp_ih0, g_bp0, g_xg0,
                        c, tile >> 4, tile & 15);
            done++;
        }
        __syncthreads();
        __threadfence();
        if (tid == 0) atomicAdd(&g_cnt_xg0[c], done);
    }
}

// =================================================================
// Worker group 1: stream xg1, gated on the h1 watermark.
// =================================================================
__device__ void worker1_body(float (*As)[68], float (*Bs)[68], int wkr)
{
    int tid = threadIdx.x;
    for (int c = 0; c < NCHUNK; c++) {
        if (tid == 0) {                       // wait for h1 chunk c
            int need = (c + 1) * 16;
            for (;;) {
                int mn = 0x7fffffff;
#pragma unroll
                for (int i = 0; i < 16; i++) {
                    int v = ld_acq(&g_wm_h1[i]);
                    mn = v < mn ? v : mn;
                }
                if (mn >= need) break;
                __nanosleep(128);
            }
        }
        __syncthreads();
        int done = 0;
        for (int tile = wkr; tile < NTILES; tile += NW1) {
            worker_tile(As, Bs, g_h, HSZ, g_Wp_ih1, g_bp1, g_xg1,
                        c, tile >> 4, tile & 15);
            done++;
        }
        __syncthreads();
        __threadfence();
        if (tid == 0) atomicAdd(&g_cnt_xg1[c], done);
    }
}

// =================================================================
// Scan body: R13-validated skeleton (fused cluster barrier, xv
// prefetch at step top under the MMA shadow). C-channel dropped
// (w2'h2' ~ 2^-22 relative, provably below the h-rep error) ->
// 6 MMA/ktile. Fast MUFU gates (sigmoid/tanh err ~3e-7).
// =================================================================
__device__ void scan_body(int bid, int role)
{
    const float*  xg = role ? g_xg1 : g_xg0;
    const __half* W1 = role ? g_W1_1 : g_W1_0;
    const __half* W2 = role ? g_W2_1 : g_W2_0;
    float* hout = role ? g_h2 : g_h;
    int* cnt = role ? g_cnt_xg1 : g_cnt_xg0;

    int tid = threadIdx.x;
    int lane = tid & 31, w = tid >> 5;
    int crank = bid & 7, cid = (bid >> 3) & 1;
    int lane4 = lane & 3, laneq = lane >> 2;

    // ---- stationary weight fragments: 2 ntiles x 16 ktiles x 2 regs ----
    unsigned w1r[2][16][2], w2r[2][16][2];
#pragma unroll
    for (int p = 0; p < 2; p++) {
        int n_g = crank * 128 + w * 16 + p * 8 + laneq;   // permuted gate row
        const unsigned* r1 = (const unsigned*)(W1 + (size_t)n_g * HSZ);
        const unsigned* r2 = (const unsigned*)(W2 + (size_t)n_g * HSZ);
#pragma unroll
        for (int kt = 0; kt < 16; kt++) {
            w1r[p][kt][0] = __ldg(r1 + kt * 8 + lane4);
            w1r[p][kt][1] = __ldg(r1 + kt * 8 + 4 + lane4);
            w2r[p][kt][0] = __ldg(r2 + kt * 8 + lane4);
            w2r[p][kt][1] = __ldg(r2 + kt * 8 + 4 + lane4);
        }
    }

    // ---- stage pointers + zero init (h_prev = 0) ----
    float* stg = g_hstage + (size_t)(role * 2 + cid) * 8192;
    for (int i = crank * 1024 + tid; i < (crank + 1) * 1024; i += 256)
        __stcg(stg + i, 0.f);

    // ---- epilogue role: (batch, hcol) per ntile ----
    bool odd = (lane & 1) != 0;
    int b_loc = laneq + (odd ? 8 : 0);
    int b_glob = cid * 16 + b_loc;
    int hcl[2];
    hcl[0] = w * 4 + (lane4 >> 1);
    hcl[1] = hcl[0] + 2;
    const float* xgp[2];
    float* hop[2];
    unsigned soff[2];
#pragma unroll
    for (int p = 0; p < 2; p++) {
        xgp[p] = xg + ((size_t)b_glob * SLEN) * G4 + crank * 128 + hcl[p] * 4;
        hop[p] = hout + ((size_t)b_glob * SLEN) * HSZ + crank * 32 + hcl[p];
        int k = crank * 32 + hcl[p];
        int kt = k >> 4, kin = k & 15, c = kin >> 1, half = kin & 1;
        int word = (c < 4 ? 0 : 2) + (b_loc < 8 ? 0 : 1);
        int lane_s = (b_loc & 7) * 4 + (c & 3);
        soff[p] = (unsigned)((((kt * 32 + lane_s) * 4 + word) * 2 + half));
    }
    float cst[2] = {0.f, 0.f};

    cluster_sync_all();   // stages zeroed cluster-wide

    const float S1 = 4.8828125e-4f;          // 2^-11

    for (int t = 0; t < SLEN; t++) {
        // ---- chunk-granular xg availability poll ----
        if ((t & 15) == 0) {
            if (tid == 0) {
                int c = t >> 4;
                while (ld_acq(&cnt[c]) < NTILES) __nanosleep(128);
            }
            __syncthreads();
        }

        int par = t & 1;
        const uint4* s1 = (const uint4*)(stg + par * 2048);
        const uint4* s2 = (const uint4*)(stg + 4096 + par * 2048);
        unsigned short* d1 = (unsigned short*)(stg + (par ^ 1) * 2048);
        unsigned short* d2 = (unsigned short*)(stg + 4096 + (par ^ 1) * 2048);

        // xg prefetch (consumed in epilogue; latency covered by MMAs)
        float4 xv0 = *(const float4*)(xgp[0] + (size_t)t * G4);
        float4 xv1 = *(const float4*)(xgp[1] + (size_t)t * G4);

        // A-fragment pipeline, depth 4 ktiles per matrix
        uint4 a1[4], a2[4];
#pragma unroll
        for (int i = 0; i < 4; i++) {
            a1[i] = __ldcg(s1 + i * 32 + lane);
            a2[i] = __ldcg(s2 + i * 32 + lane);
        }

        float A0[4] = {}, A1v[4] = {}, B0[4] = {}, B1v[4] = {};
#pragma unroll
        for (int kt = 0; kt < 16; kt++) {
            uint4 x1 = a1[kt & 3], x2 = a2[kt & 3];
            if (kt + 4 < 16) {
                a1[kt & 3] = __ldcg(s1 + (kt + 4) * 32 + lane);
                a2[kt & 3] = __ldcg(s2 + (kt + 4) * 32 + lane);
            }
            mma_f16(A0,  x1, w1r[0][kt][0], w1r[0][kt][1]);
            mma_f16(A1v, x1, w1r[1][kt][0], w1r[1][kt][1]);
            mma_f16(B0,  x2, w1r[0][kt][0], w1r[0][kt][1]);
            mma_f16(B1v, x2, w1r[1][kt][0], w1r[1][kt][1]);
            mma_f16(B0,  x1, w2r[0][kt][0], w2r[0][kt][1]);
            mma_f16(B1v, x1, w2r[1][kt][0], w2r[1][kt][1]);
        }

#pragma unroll
        for (int p = 0; p < 2; p++) {
            float* A = p ? A1v : A0;
            float* B = p ? B1v : B0;
            float g4[4];
#pragma unroll
            for (int i = 0; i < 4; i++)
                g4[i] = fmaf(S1, B[i], A[i]);
            float e0 = __shfl_xor_sync(0xffffffffu, g4[0], 1);
            float e1 = __shfl_xor_sync(0xffffffffu, g4[1], 1);
            float e2 = __shfl_xor_sync(0xffffffffu, g4[2], 1);
            float e3 = __shfl_xor_sync(0xffffffffu, g4[3], 1);
            float gi, gf, gg, go;
            if (!odd) { gi = g4[0]; gf = g4[1]; gg = e0; go = e1; }
            else      { gi = e2;   gf = e3;   gg = g4[2]; go = g4[3]; }
            float4 xv = p ? xv1 : xv0;
            gi += xv.x; gf += xv.y; gg += xv.z; go += xv.w;
            float si = fast_sigmoid(gi);
            float sf = fast_sigmoid(gf);
            float so = fast_sigmoid(go);
            float tg = fast_tanh(gg);
            cst[p] = fmaf(sf, cst[p], si * tg);
            float h = so * fast_tanh(cst[p]);
            hop[p][(size_t)t * HSZ] = h;
            __half h1 = __float2half_rn(h);
            float r = (h - __half2float(h1)) * 2048.f;
            __half h2 = __float2half_rn(r);
            st16cg(d1 + soff[p], __half_as_ushort(h1));
            st16cg(d2 + soff[p], __half_as_ushort(h2));
        }
        cluster_sync_all();   // release h stores / acquire peers' stage

        // ---- publish h1 watermark (layer 0 only), every 16 steps ----
        if (role == 0 && (t & 15) == 15 && tid == 0) {
            __threadfence();
            st_rel(&g_wm_h1[cid * 8 + crank], t + 1);
        }
    }
}

// =================================================================
// Mega kernel: 12 clusters / 96 CTAs.
//   CTAs  0-31 : scans (clusters 0-1 layer 0, clusters 2-3 layer 1)
//   CTAs 32-63 : xg0 streamers (no deps, runs ahead of scan0)
//   CTAs 64-95 : xg1 streamers (gated on h1 watermark)
// =================================================================
__global__ __launch_bounds__(256, 1) __cluster_dims__(8, 1, 1)
void fused_pipeline(const float* __restrict__ x)
{
    __shared__ __align__(16) float As[16][68];
    __shared__ __align__(16) float Bs[16][68];
    int bid = blockIdx.x;
    if (bid < 32)      scan_body(bid & 15, bid >> 4);
    else if (bid < 64) worker0_body(As, Bs, bid - 32, x);
    else               worker1_body(As, Bs, bid - 64);
}

// =================================================================
// kNN over quantum memory: per token -> 3 indices + 3 scaled weights
// =================================================================
__global__ __launch_bounds__(256) void knn_kernel(
    const float* __restrict__ lstm,
    const float* __restrict__ Wcq, const float* __restrict__ bcq,
    const float* __restrict__ keys, const float* __restrict__ qwp,
    float* __restrict__ wout, int* __restrict__ idxout)
{
    __shared__ float sWcq[QDIM][HSZ];
    __shared__ float skn[MMEM][QDIM];
    __shared__ __align__(16) float sh[8][HSZ];
    __shared__ float sq[8][QDIM];
    __shared__ float ssims[8][MMEM];
    int tid = threadIdx.x;
    for (int i = tid; i < QDIM * HSZ; i += 256)
        sWcq[i >> 8][i & 255] = Wcq[i];
    if (tid < MMEM) {
        float kv[QDIM]; float nrm = 0.f;
#pragma unroll
        for (int d = 0; d < QDIM; d++) { kv[d] = keys[tid * QDIM + d]; nrm += kv[d] * kv[d]; }
        float inv = 1.f / (sqrtf(nrm) + 1e-8f);
#pragma unroll
        for (int d = 0; d < QDIM; d++) skn[tid][d] = kv[d] * inv;
    }
    __syncthreads();

    int wid = tid >> 5, lane = tid & 31;
    int token = blockIdx.x * 8 + wid;
    const float* hrow = lstm + (size_t)token * HSZ;
    for (int i = lane; i < HSZ / 4; i += 32)
        ((float4*)sh[wid])[i] = ((const float4*)hrow)[i];
    __syncwarp();
    if (lane < QDIM) {
        float acc = bcq[lane];
#pragma unroll 8
        for (int k = 0; k < HSZ; k++) acc = fmaf(sWcq[lane][k], sh[wid][k], acc);
        sq[wid][lane] = tanhf(acc);
    }
    __syncwarp();
    float qn[QDIM];
    {
        float nrm = 0.f;
#pragma unroll
        for (int d = 0; d < QDIM; d++) { float v = sq[wid][d]; nrm += v * v; }
        float inv = 1.f / (sqrtf(nrm) + 1e-8f);
#pragma unroll
        for (int d = 0; d < QDIM; d++) qn[d] = sq[wid][d] * inv;
    }
#pragma unroll
    for (int mm = 0; mm < 2; mm++) {
        int m = lane + mm * 32;
        float s = 0.f;
#pragma unroll
        for (int d = 0; d < QDIM; d++) s = fmaf(qn[d], skn[m][d], s);
        ssims[wid][m] = s;
    }
    __syncwarp();
    if (lane == 0) {
        float v0 = -1e30f, v1 = -1e30f, v2 = -1e30f;
        int i0 = 0, i1 = 0, i2 = 0;
        for (int m = 0; m < MMEM; m++) {
            float s = ssims[wid][m];
            if (s > v0)      { v2 = v1; i2 = i1; v1 = v0; i1 = i0; v0 = s; i0 = m; }
            else if (s > v1) { v2 = v1; i2 = i1; v1 = s;  i1 = m; }
            else if (s > v2) { v2 = s;  i2 = m; }
        }
        float tot = v0 + v1 + v2;
        float qw = *qwp;
        float sc = (tot > 0.f) ? (qw / tot) : 0.f;
        wout[token * 4 + 0] = v0 * sc;
        wout[token * 4 + 1] = v1 * sc;
        wout[token * 4 + 2] = v2 * sc;
        idxout[token * 4 + 0] = i0;
        idxout[token * 4 + 1] = i1;
        idxout[token * 4 + 2] = i2;
    }
}

// =================================================================
// Output GEMM with fused quantum-memory epilogue
// =================================================================
__global__ __launch_bounds__(256) void out_gemm_kernel(
    const float* __restrict__ A, int lda,
    const float* __restrict__ B, int ldb,
    float* __restrict__ C, int ldc,
    int K,
    const float* __restrict__ bout,
    const float* __restrict__ cwp,
    const float* __restrict__ wts,
    const int*   __restrict__ idxs,
    const float* __restrict__ MV)
{
    __shared__ __align__(16) float As[16][68];
    __shared__ __align__(16) float Bs[16][68];
    int tid = threadIdx.x;
    int bm = blockIdx.y * 64, bn = blockIdx.x * 64;
    int lr = tid >> 2, lk = (tid & 3) * 4;
    int tx = tid & 15, ty = tid >> 4;
    float acc[4][4] = {};
    const float* Ap = A + (size_t)(bm + lr) * lda + lk;
    const float* Bp = B + (size_t)(bn + lr) * ldb + lk;

    for (int k0 = 0; k0 < K; k0 += 16) {
        float4 av = *(const float4*)(Ap + k0);
        float4 bv = *(const float4*)(Bp + k0);
        As[lk + 0][lr] = av.x; As[lk + 1][lr] = av.y;
        As[lk + 2][lr] = av.z; As[lk + 3][lr] = av.w;
        Bs[lk + 0][lr] = bv.x; Bs[lk + 1][lr] = bv.y;
        Bs[lk + 2][lr] = bv.z; Bs[lk + 3][lr] = bv.w;
        __syncthreads();
#pragma unroll
        for (int kk = 0; kk < 16; kk++) {
            float4 a4 = *(const float4*)&As[kk][ty * 4];
            float4 b4 = *(const float4*)&Bs[kk][tx * 4];
            float a[4] = {a4.x, a4.y, a4.z, a4.w};
            float b[4] = {b4.x, b4.y, b4.z, b4.w};
#pragma unroll
            for (int i = 0; i < 4; i++)
#pragma unroll
                for (int j = 0; j < 4; j++)
                    acc[i][j] = fmaf(a[i], b[j], acc[i][j]);
        }
        __syncthreads();
    }

    float cw = *cwp;
#pragma unroll
    for (int i = 0; i < 4; i++) {
        int m = bm + ty * 4 + i;
        float w0 = wts[m * 4 + 0], w1 = wts[m * 4 + 1], w2 = wts[m * 4 + 2];
        int   i0 = idxs[m * 4 + 0], i1 = idxs[m * 4 + 1], i2 = idxs[m * 4 + 2];
        const float* mv0 = MV + (size_t)i0 * HSZ;
        const float* mv1 = MV + (size_t)i1 * HSZ;
        const float* mv2 = MV + (size_t)i2 * HSZ;
        float out4[4];
#pragma unroll
        for (int j = 0; j < 4; j++) {
            int n = bn + tx * 4 + j;
            float v = cw * acc[i][j] + bout[n];
            v = fmaf(w0, mv0[n], v);
            v = fmaf(w1, mv1[n], v);
            v = fmaf(w2, mv2[n], v);
            out4[j] = v;
        }
        *(float4*)&C[(size_t)m * ldc + bn + tx * 4] =
            make_float4(out4[0], out4[1], out4[2], out4[3]);
    }
}

// =================================================================
extern "C" void kernel_launch(void* const* d_in, const int* in_sizes, int n_in,
                              void* d_out, int out_size) {
    const float* x      = (const float*)d_in[0];
    const float* W_ih0  = (const float*)d_in[1];
    const float* W_hh0  = (const float*)d_in[2];
    const float* b_ih0  = (const float*)d_in[3];
    const float* b_hh0  = (const float*)d_in[4];
    const float* W_ih1  = (const float*)d_in[5];
    const float* W_hh1  = (const float*)d_in[6];
    const float* b_ih1  = (const float*)d_in[7];
    const float* b_hh1  = (const float*)d_in[8];
    const float* W_cq   = (const float*)d_in[9];
    const float* b_cq   = (const float*)d_in[10];
    const float* mkeys  = (const float*)d_in[11];
    const float* mvals  = (const float*)d_in[12];
    const float* W_out  = (const float*)d_in[13];
    const float* b_out  = (const float*)d_in[14];
    const float* cw     = (const float*)d_in[15];
    const float* qw     = (const float*)d_in[16];
    float* out = (float*)d_out;

    float* hbf2 = nullptr; cudaGetSymbolAddress((void**)&hbf2, g_h2);
    float* mv   = nullptr; cudaGetSymbolAddress((void**)&mv,   g_mv);
    float* wts  = nullptr; cudaGetSymbolAddress((void**)&wts,  g_w);
    int*   idx  = nullptr; cudaGetSymbolAddress((void**)&idx,  g_idx);

    // #1 zero pipeline sync state (graph-replay safe)
    zero_sync_kernel<<<1, 128>>>();

    // #2 permute weights/biases + fp16 split of W_hh
    prep_kernel<<<G4, 256>>>(W_hh0, W_hh1, W_ih0, W_ih1,
                             b_ih0, b_hh0, b_ih1, b_hh1);
    // #3 MV = mem_vals @ Wq^T
    mv_kernel<<<MMEM, HSZ>>>(mvals, W_out, mv);

    // #4 fused pipeline: xg0 streamers + both scans + xg1 streamers
    fused_pipeline<<<96, 256>>>(x);

    // #5 kNN metadata
    knn_kernel<<<NTOK / 8, 256>>>(hbf2, W_cq, b_cq, mkeys, qw, wts, idx);

    // #6 out = cw*(lstm@Wc^T) + b_out + sum_k w_k*MV[idx_k]
    {
        dim3 grid(HSZ / 64, NTOK / 64);
        out_gemm_kernel<<<grid, 256>>>(hbf2, HSZ, W_out, 2 * HSZ, out, HSZ, HSZ,
                                       b_out, cw, wts, idx, mv);
    }
}

// round 17
// speedup vs baseline: 1.0925x; 1.0925x over previous
#include <cuda_runtime.h>
#include <cuda_bf16.h>
#include <cuda_fp16.h>
#include <math.h>
#include <stdint.h>

#define NBATCH 32
#define SLEN   2048
#define NIN    128
#define HSZ    256
#define G4     1024
#define NTOK   (NBATCH * SLEN)   // 65536
#define QDIM   16
#define MMEM   64
#define NCHUNK 128               // 2048 steps / 16 per chunk
#define NTILES 128               // xg tiles per chunk (8 M x 16 N)
#define NW0    32                // xg0 worker CTAs
#define NW1    32                // xg1 worker CTAs

// ---------------- static scratch (allocation-free) ----------------
__device__ float g_xg0[(size_t)NTOK * G4];  // permuted xg, layer 0
__device__ float g_xg1[(size_t)NTOK * G4];  // permuted xg, layer 1
__device__ float g_h  [(size_t)NTOK * HSZ]; // h1 (layer-0 output)
__device__ float g_h2 [(size_t)NTOK * HSZ]; // lstm_out (layer-1 output)
__device__ float g_mv[MMEM * HSZ];          // mem_vals @ Wq^T
// permuted W_hh split: w1 = fp16(w), w2s = fp16((w - w1) * 2^11)
__device__ __half g_W1_0[G4 * HSZ];
__device__ __half g_W2_0[G4 * HSZ];
__device__ __half g_W1_1[G4 * HSZ];
__device__ __half g_W2_1[G4 * HSZ];
__device__ float g_Wp_ih0[G4 * NIN];
__device__ float g_Wp_ih1[G4 * HSZ];
__device__ float g_bp0[G4];
__device__ float g_bp1[G4];
// h stage: [role 2][cid 2][mat 2][parity 2][2048 u32 words]
__device__ float g_hstage[4 * 8192];
// pipeline sync
__device__ int g_cnt_xg0[NCHUNK];
__device__ int g_cnt_xg1[NCHUNK];
__device__ int g_wm_h1[16];

// =================================================================
// sync helpers
// =================================================================
__device__ __forceinline__ int ld_acq(const int* p) {
    int v;
    asm volatile("ld.acquire.gpu.u32 %0, [%1];" : "=r"(v) : "l"(p) : "memory");
    return v;
}
__device__ __forceinline__ void st_rel(int* p, int v) {
    asm volatile("st.release.gpu.u32 [%0], %1;" :: "l"(p), "r"(v) : "memory");
}
__device__ __forceinline__ void cluster_sync_all() {
    asm volatile("barrier.cluster.arrive.aligned;" ::: "memory");
    asm volatile("barrier.cluster.wait.aligned;" ::: "memory");
}
__device__ __forceinline__ void mma_f16(float* d, const uint4& a,
                                        unsigned b0, unsigned b1) {
    asm volatile(
        "mma.sync.aligned.m16n8k16.row.col.f32.f16.f16.f32 "
        "{%0,%1,%2,%3},{%4,%5,%6,%7},{%8,%9},{%0,%1,%2,%3};"
        : "+f"(d[0]), "+f"(d[1]), "+f"(d[2]), "+f"(d[3])
        : "r"(a.x), "r"(a.y), "r"(a.z), "r"(a.w), "r"(b0), "r"(b1));
}
__device__ __forceinline__ void st16cg(void* p, unsigned short v) {
    asm volatile("st.global.cg.b16 [%0], %1;" :: "l"(p), "h"(v) : "memory");
}

// =================================================================
// zero pipeline sync state (run at start of every launch / replay)
// =================================================================
__global__ void zero_sync_kernel() {
    int i = threadIdx.x;
    if (i < NCHUNK) { g_cnt_xg0[i] = 0; g_cnt_xg1[i] = 0; }
    if (i < 16)     g_wm_h1[i] = 0;
}

// =================================================================
// Weight/bias permutation + fp16 hi/scaled-lo split for W_hh
// =================================================================
__global__ void prep_kernel(const float* __restrict__ Whh0,
                            const float* __restrict__ Whh1,
                            const float* __restrict__ Wih0,
                            const float* __restrict__ Wih1,
                            const float* __restrict__ bih0,
                            const float* __restrict__ bhh0,
                            const float* __restrict__ bih1,
                            const float* __restrict__ bhh1)
{
    int p = blockIdx.x;                   // permuted row 0..1023
    int src = (p & 3) * HSZ + (p >> 2);   // gate = p&3, hcol = p>>2
    int tid = threadIdx.x;
    for (int k = tid; k < HSZ; k += blockDim.x) {
        float v0 = Whh0[src * HSZ + k];
        __half a0 = __float2half_rn(v0);
        g_W1_0[p * HSZ + k] = a0;
        g_W2_0[p * HSZ + k] = __float2half_rn((v0 - __half2float(a0)) * 2048.f);
        float v1 = Whh1[src * HSZ + k];
        __half a1 = __float2half_rn(v1);
        g_W1_1[p * HSZ + k] = a1;
        g_W2_1[p * HSZ + k] = __float2half_rn((v1 - __half2float(a1)) * 2048.f);
        g_Wp_ih1[p * HSZ + k] = Wih1[src * HSZ + k];
    }
    for (int k = tid; k < NIN; k += blockDim.x)
        g_Wp_ih0[p * NIN + k] = Wih0[src * NIN + k];
    if (tid == 0) {
        g_bp0[p] = bih0[src] + bhh0[src];
        g_bp1[p] = bih1[src] + bhh1[src];
    }
}

// =================================================================
// MV[m][h] = sum_h' mem_vals[m][h'] * W_out[h][256 + h']
// =================================================================
__global__ void mv_kernel(const float* __restrict__ vals,
                          const float* __restrict__ Wout,
                          float* __restrict__ mv)
{
    int m = blockIdx.x, h = threadIdx.x;
    const float* vrow = vals + (size_t)m * HSZ;
    const float* wrow = Wout + (size_t)h * 2 * HSZ + HSZ;
    float acc = 0.f;
#pragma unroll 8
    for (int k = 0; k < HSZ; k++) acc = fmaf(vrow[k], wrow[k], acc);
    mv[(size_t)m * HSZ + h] = acc;
}

// =================================================================
// Worker GEMM tile: one 64x64 tile of a 16-token xg chunk.
// =================================================================
__device__ void worker_tile(float (*As)[68], float (*Bs)[68],
                            const float* __restrict__ Asrc, int lda,
                            const float* __restrict__ B,
                            const float* __restrict__ bias,
                            float* __restrict__ C,
                            int chunk, int mtile, int ntile)
{
    int tid = threadIdx.x;
    int lr = tid >> 2, lk = (tid & 3) * 4;
    int tx = tid & 15, ty = tid >> 4;
    int mrow = mtile * 64 + lr;
    int b = mrow >> 4, ti = mrow & 15;
    const float* Ap = Asrc + ((size_t)b * SLEN + chunk * 16 + ti) * lda + lk;
    const float* Bp = B + (size_t)(ntile * 64 + lr) * lda + lk;
    float acc[4][4] = {};

    for (int k0 = 0; k0 < lda; k0 += 16) {
        float4 av = *(const float4*)(Ap + k0);
        float4 bv = *(const float4*)(Bp + k0);
        As[lk + 0][lr] = av.x; As[lk + 1][lr] = av.y;
        As[lk + 2][lr] = av.z; As[lk + 3][lr] = av.w;
        Bs[lk + 0][lr] = bv.x; Bs[lk + 1][lr] = bv.y;
        Bs[lk + 2][lr] = bv.z; Bs[lk + 3][lr] = bv.w;
        __syncthreads();
#pragma unroll
        for (int kk = 0; kk < 16; kk++) {
            float4 a4 = *(const float4*)&As[kk][ty * 4];
            float4 b4 = *(const float4*)&Bs[kk][tx * 4];
            float a[4] = {a4.x, a4.y, a4.z, a4.w};
            float bb[4] = {b4.x, b4.y, b4.z, b4.w};
#pragma unroll
            for (int i = 0; i < 4; i++)
#pragma unroll
                for (int j = 0; j < 4; j++)
                    acc[i][j] = fmaf(a[i], bb[j], acc[i][j]);
        }
        __syncthreads();
    }

    int bn = ntile * 64;
    float bcol[4];
#pragma unroll
    for (int j = 0; j < 4; j++) bcol[j] = bias[bn + tx * 4 + j];
#pragma unroll
    for (int i = 0; i < 4; i++) {
        int mr = mtile * 64 + ty * 4 + i;
        int b2 = mr >> 4, t2 = mr & 15;
        size_t row = (size_t)b2 * SLEN + chunk * 16 + t2;
        float4 o;
        o.x = acc[i][0] + bcol[0];
        o.y = acc[i][1] + bcol[1];
        o.z = acc[i][2] + bcol[2];
        o.w = acc[i][3] + bcol[3];
        *(float4*)&C[row * G4 + bn + tx * 4] = o;
    }
}

// =================================================================
// Worker group 0: stream xg0 (no deps, runs ahead freely).
// =================================================================
__device__ void worker0_body(float (*As)[68], float (*Bs)[68],
                             int wkr, const float* __restrict__ x)
{
    int tid = threadIdx.x;
    for (int c = 0; c < NCHUNK; c++) {
        int done = 0;
        for (int tile = wkr; tile < NTILES; tile += NW0) {
            worker_tile(As, Bs, x, NIN, g_Wp_ih0, g_bp0, g_xg0,
                        c, tile >> 4, tile & 15);
            done++;
        }
        __syncthreads();
        __threadfence();
        if (tid == 0) atomicAdd(&g_cnt_xg0[c], done);
    }
}

// =================================================================
// Worker group 1: stream xg1, gated on the h1 watermark.
// =================================================================
__device__ void worker1_body(float (*As)[68], float (*Bs)[68], int wkr)
{
    int tid = threadIdx.x;
    for (int c = 0; c < NCHUNK; c++) {
        if (tid == 0) {                       // wait for h1 chunk c
            int need = (c + 1) * 16;
            for (;;) {
                int mn = 0x7fffffff;
#pragma unroll
                for (int i = 0; i < 16; i++) {
                    int v = ld_acq(&g_wm_h1[i]);
                    mn = v < mn ? v : mn;
                }
                if (mn >= need) break;
                __nanosleep(128);
            }
        }
        __syncthreads();
        int done = 0;
        for (int tile = wkr; tile < NTILES; tile += NW1) {
            worker_tile(As, Bs, g_h, HSZ, g_Wp_ih1, g_bp1, g_xg1,
                        c, tile >> 4, tile & 15);
            done++;
        }
        __syncthreads();
        __threadfence();
        if (tid == 0) atomicAdd(&g_cnt_xg1[c], done);
    }
}

// =================================================================
// Scan body: EXACT R13 winner configuration (8 MMA/kt incl. C
// channel, precise gates, fused cluster barrier, xv prefetch at
// step top under the MMA shadow). Do not touch.
// =================================================================
__device__ void scan_body(int bid, int role)
{
    const float*  xg = role ? g_xg1 : g_xg0;
    const __half* W1 = role ? g_W1_1 : g_W1_0;
    const __half* W2 = role ? g_W2_1 : g_W2_0;
    float* hout = role ? g_h2 : g_h;
    int* cnt = role ? g_cnt_xg1 : g_cnt_xg0;

    int tid = threadIdx.x;
    int lane = tid & 31, w = tid >> 5;
    int crank = bid & 7, cid = (bid >> 3) & 1;
    int lane4 = lane & 3, laneq = lane >> 2;

    // ---- stationary weight fragments: 2 ntiles x 16 ktiles x 2 regs ----
    unsigned w1r[2][16][2], w2r[2][16][2];
#pragma unroll
    for (int p = 0; p < 2; p++) {
        int n_g = crank * 128 + w * 16 + p * 8 + laneq;   // permuted gate row
        const unsigned* r1 = (const unsigned*)(W1 + (size_t)n_g * HSZ);
        const unsigned* r2 = (const unsigned*)(W2 + (size_t)n_g * HSZ);
#pragma unroll
        for (int kt = 0; kt < 16; kt++) {
            w1r[p][kt][0] = __ldg(r1 + kt * 8 + lane4);
            w1r[p][kt][1] = __ldg(r1 + kt * 8 + 4 + lane4);
            w2r[p][kt][0] = __ldg(r2 + kt * 8 + lane4);
            w2r[p][kt][1] = __ldg(r2 + kt * 8 + 4 + lane4);
        }
    }

    // ---- stage pointers + zero init (h_prev = 0) ----
    float* stg = g_hstage + (size_t)(role * 2 + cid) * 8192;
    for (int i = crank * 1024 + tid; i < (crank + 1) * 1024; i += 256)
        __stcg(stg + i, 0.f);

    // ---- epilogue role: (batch, hcol) per ntile ----
    bool odd = (lane & 1) != 0;
    int b_loc = laneq + (odd ? 8 : 0);
    int b_glob = cid * 16 + b_loc;
    int hcl[2];
    hcl[0] = w * 4 + (lane4 >> 1);
    hcl[1] = hcl[0] + 2;
    const float* xgp[2];
    float* hop[2];
    unsigned soff[2];
#pragma unroll
    for (int p = 0; p < 2; p++) {
        xgp[p] = xg + ((size_t)b_glob * SLEN) * G4 + crank * 128 + hcl[p] * 4;
        hop[p] = hout + ((size_t)b_glob * SLEN) * HSZ + crank * 32 + hcl[p];
        int k = crank * 32 + hcl[p];
        int kt = k >> 4, kin = k & 15, c = kin >> 1, half = kin & 1;
        int word = (c < 4 ? 0 : 2) + (b_loc < 8 ? 0 : 1);
        int lane_s = (b_loc & 7) * 4 + (c & 3);
        soff[p] = (unsigned)((((kt * 32 + lane_s) * 4 + word) * 2 + half));
    }
    float cst[2] = {0.f, 0.f};

    cluster_sync_all();   // stages zeroed cluster-wide

    const float S1 = 4.8828125e-4f;          // 2^-11

    for (int t = 0; t < SLEN; t++) {
        // ---- chunk-granular xg availability poll ----
        if ((t & 15) == 0) {
            if (tid == 0) {
                int c = t >> 4;
                while (ld_acq(&cnt[c]) < NTILES) __nanosleep(128);
            }
            __syncthreads();
        }

        int par = t & 1;
        const uint4* s1 = (const uint4*)(stg + par * 2048);
        const uint4* s2 = (const uint4*)(stg + 4096 + par * 2048);
        unsigned short* d1 = (unsigned short*)(stg + (par ^ 1) * 2048);
        unsigned short* d2 = (unsigned short*)(stg + 4096 + (par ^ 1) * 2048);

        // xg prefetch (consumed in epilogue; latency covered by MMAs)
        float4 xv0 = *(const float4*)(xgp[0] + (size_t)t * G4);
        float4 xv1 = *(const float4*)(xgp[1] + (size_t)t * G4);

        // A-fragment pipeline, depth 4 ktiles per matrix
        uint4 a1[4], a2[4];
#pragma unroll
        for (int i = 0; i < 4; i++) {
            a1[i] = __ldcg(s1 + i * 32 + lane);
            a2[i] = __ldcg(s2 + i * 32 + lane);
        }

        float A0[4] = {}, A1v[4] = {}, B0[4] = {}, B1v[4] = {};
        float C0[4] = {}, C1v[4] = {};
#pragma unroll
        for (int kt = 0; kt < 16; kt++) {
            uint4 x1 = a1[kt & 3], x2 = a2[kt & 3];
            if (kt + 4 < 16) {
                a1[kt & 3] = __ldcg(s1 + (kt + 4) * 32 + lane);
                a2[kt & 3] = __ldcg(s2 + (kt + 4) * 32 + lane);
            }
            mma_f16(A0,  x1, w1r[0][kt][0], w1r[0][kt][1]);
            mma_f16(A1v, x1, w1r[1][kt][0], w1r[1][kt][1]);
            mma_f16(B0,  x2, w1r[0][kt][0], w1r[0][kt][1]);
            mma_f16(B1v, x2, w1r[1][kt][0], w1r[1][kt][1]);
            mma_f16(B0,  x1, w2r[0][kt][0], w2r[0][kt][1]);
            mma_f16(B1v, x1, w2r[1][kt][0], w2r[1][kt][1]);
            mma_f16(C0,  x2, w2r[0][kt][0], w2r[0][kt][1]);
            mma_f16(C1v, x2, w2r[1][kt][0], w2r[1][kt][1]);
        }

#pragma unroll
        for (int p = 0; p < 2; p++) {
            float* A = p ? A1v : A0;
            float* B = p ? B1v : B0;
            float* C = p ? C1v : C0;
            float g4[4];
#pragma unroll
            for (int i = 0; i < 4; i++)
                g4[i] = fmaf(S1, fmaf(S1, C[i], B[i]), A[i]);
            float e0 = __shfl_xor_sync(0xffffffffu, g4[0], 1);
            float e1 = __shfl_xor_sync(0xffffffffu, g4[1], 1);
            float e2 = __shfl_xor_sync(0xffffffffu, g4[2], 1);
            float e3 = __shfl_xor_sync(0xffffffffu, g4[3], 1);
            float gi, gf, gg, go;
            if (!odd) { gi = g4[0]; gf = g4[1]; gg = e0; go = e1; }
            else      { gi = e2;   gf = e3;   gg = g4[2]; go = g4[3]; }
            float4 xv = p ? xv1 : xv0;
            gi += xv.x; gf += xv.y; gg += xv.z; go += xv.w;
            float si = 1.f / (1.f + expf(-gi));
            float sf = 1.f / (1.f + expf(-gf));
            float so = 1.f / (1.f + expf(-go));
            float tg = tanhf(gg);
            cst[p] = fmaf(sf, cst[p], si * tg);
            float h = so * tanhf(cst[p]);
            hop[p][(size_t)t * HSZ] = h;
            __half h1 = __float2half_rn(h);
            float r = (h - __half2float(h1)) * 2048.f;
            __half h2 = __float2half_rn(r);
            st16cg(d1 + soff[p], __half_as_ushort(h1));
            st16cg(d2 + soff[p], __half_as_ushort(h2));
        }
        cluster_sync_all();   // release h stores / acquire peers' stage

        // ---- publish h1 watermark (layer 0 only), every 16 steps ----
        if (role == 0 && (t & 15) == 15 && tid == 0) {
            __threadfence();
            st_rel(&g_wm_h1[cid * 8 + crank], t + 1);
        }
    }
}

// =================================================================
// Mega kernel: 12 clusters / 96 CTAs.
//   CTAs  0-31 : scans (clusters 0-1 layer 0, clusters 2-3 layer 1)
//   CTAs 32-63 : xg0 streamers (no deps, runs ahead of scan0)
//   CTAs 64-95 : xg1 streamers (gated on h1 watermark)
// =================================================================
__global__ __launch_bounds__(256, 1) __cluster_dims__(8, 1, 1)
void fused_pipeline(const float* __restrict__ x)
{
    __shared__ __align__(16) float As[16][68];
    __shared__ __align__(16) float Bs[16][68];
    int bid = blockIdx.x;
    if (bid < 32)      scan_body(bid & 15, bid >> 4);
    else if (bid < 64) worker0_body(As, Bs, bid - 32, x);
    else               worker1_body(As, Bs, bid - 64);
}

// =================================================================
// Fused tail: per 64-token group, kNN (weights/indices kept in smem)
// then the four 64x64 K=256 output tiles with the quantum-memory
// epilogue. Full-chip standalone kernel after the mega.
// =================================================================
__global__ __launch_bounds__(256) void tail_kernel(
    const float* __restrict__ Wcq, const float* __restrict__ bcq,
    const float* __restrict__ keys, const float* __restrict__ qwp,
    const float* __restrict__ Wout, const float* __restrict__ bout,
    const float* __restrict__ cwp, float* __restrict__ outp)
{
    __shared__ float sWcq[QDIM][HSZ];
    __shared__ float skn[MMEM][QDIM];
    __shared__ __align__(16) float sh[8][HSZ];
    __shared__ float sq[8][QDIM];
    __shared__ float ssims[8][MMEM];
    __shared__ float sw[64][3];
    __shared__ int   sidx[64][3];
    __shared__ __align__(16) float As[16][68];
    __shared__ __align__(16) float Bs[16][68];

    int tid = threadIdx.x;
    int wid = tid >> 5, lane = tid & 31;
    size_t base = (size_t)blockIdx.x * 64;     // first flat token of group

    for (int i = tid; i < QDIM * HSZ; i += 256)
        sWcq[i >> 8][i & 255] = Wcq[i];
    if (tid < MMEM) {
        float kv[QDIM]; float nrm = 0.f;
#pragma unroll
        for (int d = 0; d < QDIM; d++) {
            kv[d] = keys[tid * QDIM + d]; nrm += kv[d] * kv[d];
        }
        float inv = 1.f / (sqrtf(nrm) + 1e-8f);
#pragma unroll
        for (int d = 0; d < QDIM; d++) skn[tid][d] = kv[d] * inv;
    }
    __syncthreads();

    float qw = *qwp, cw = *cwp;

    // ---- kNN for the 64 tokens (8 warps x 8 iterations) ----
    for (int it = 0; it < 8; it++) {
        int r = it * 8 + wid;
        size_t token = base + r;
        const float* hrow = g_h2 + token * HSZ;
        for (int i = lane; i < HSZ / 4; i += 32)
            ((float4*)sh[wid])[i] = ((const float4*)hrow)[i];
        __syncwarp();
        if (lane < QDIM) {
            float acc = bcq[lane];
#pragma unroll 8
            for (int k = 0; k < HSZ; k++)
                acc = fmaf(sWcq[lane][k], sh[wid][k], acc);
            sq[wid][lane] = tanhf(acc);
        }
        __syncwarp();
        float qn[QDIM];
        {
            float nrm = 0.f;
#pragma unroll
            for (int d = 0; d < QDIM; d++) {
                float v = sq[wid][d]; nrm += v * v;
            }
            float inv = 1.f / (sqrtf(nrm) + 1e-8f);
#pragma unroll
            for (int d = 0; d < QDIM; d++) qn[d] = sq[wid][d] * inv;
        }
#pragma unroll
        for (int mm = 0; mm < 2; mm++) {
            int mk = lane + mm * 32;
            float s = 0.f;
#pragma unroll
            for (int d = 0; d < QDIM; d++) s = fmaf(qn[d], skn[mk][d], s);
            ssims[wid][mk] = s;
        }
        __syncwarp();
        if (lane == 0) {
            float v0 = -1e30f, v1 = -1e30f, v2 = -1e30f;
            int i0 = 0, i1 = 0, i2 = 0;
            for (int mk = 0; mk < MMEM; mk++) {
                float s = ssims[wid][mk];
                if (s > v0)      { v2 = v1; i2 = i1; v1 = v0; i1 = i0;
                                   v0 = s; i0 = mk; }
                else if (s > v1) { v2 = v1; i2 = i1; v1 = s; i1 = mk; }
                else if (s > v2) { v2 = s;  i2 = mk; }
            }
            float tot = v0 + v1 + v2;
            float sc = (tot > 0.f) ? (qw / tot) : 0.f;
            sw[r][0] = v0 * sc; sw[r][1] = v1 * sc; sw[r][2] = v2 * sc;
            sidx[r][0] = i0; sidx[r][1] = i1; sidx[r][2] = i2;
        }
        __syncwarp();
    }
    __syncthreads();   // sw/sidx visible CTA-wide

    // ---- four output tiles: rows base..base+63, K=256, ldb=512 ----
    int lr = tid >> 2, lk = (tid & 3) * 4;
    int tx = tid & 15, ty = tid >> 4;
    for (int nt = 0; nt < 4; nt++) {
        const float* Ap = g_h2 + (base + lr) * HSZ + lk;
        const float* Bp = Wout + (size_t)(nt * 64 + lr) * 2 * HSZ + lk;
        float acc[4][4] = {};
        for (int k0 = 0; k0 < HSZ; k0 += 16) {
            float4 av = *(const float4*)(Ap + k0);
            float4 bv = *(const float4*)(Bp + k0);
            As[lk + 0][lr] = av.x; As[lk + 1][lr] = av.y;
            As[lk + 2][lr] = av.z; As[lk + 3][lr] = av.w;
            Bs[lk + 0][lr] = bv.x; Bs[lk + 1][lr] = bv.y;
            Bs[lk + 2][lr] = bv.z; Bs[lk + 3][lr] = bv.w;
            __syncthreads();
#pragma unroll
            for (int kk = 0; kk < 16; kk++) {
                float4 a4 = *(const float4*)&As[kk][ty * 4];
                float4 b4 = *(const float4*)&Bs[kk][tx * 4];
                float a[4] = {a4.x, a4.y, a4.z, a4.w};
                float bb[4] = {b4.x, b4.y, b4.z, b4.w};
#pragma unroll
                for (int i = 0; i < 4; i++)
#pragma unroll
                    for (int j = 0; j < 4; j++)
                        acc[i][j] = fmaf(a[i], bb[j], acc[i][j]);
            }
            __syncthreads();
        }
        int bn = nt * 64;
#pragma unroll
        for (int i = 0; i < 4; i++) {
            int r = ty * 4 + i;
            size_t token = base + r;
            float w0 = sw[r][0], w1 = sw[r][1], w2 = sw[r][2];
            const float* mv0 = g_mv + (size_t)sidx[r][0] * HSZ;
            const float* mv1 = g_mv + (size_t)sidx[r][1] * HSZ;
            const float* mv2 = g_mv + (size_t)sidx[r][2] * HSZ;
            float o4[4];
#pragma unroll
            for (int j = 0; j < 4; j++) {
                int n = bn + tx * 4 + j;
                float v = cw * acc[i][j] + bout[n];
                v = fmaf(w0, mv0[n], v);
                v = fmaf(w1, mv1[n], v);
                v = fmaf(w2, mv2[n], v);
                o4[j] = v;
            }
            *(float4*)&outp[token * HSZ + bn + tx * 4] =
                make_float4(o4[0], o4[1], o4[2], o4[3]);
        }
    }
}

// =================================================================
extern "C" void kernel_launch(void* const* d_in, const int* in_sizes, int n_in,
                              void* d_out, int out_size) {
    const float* x      = (const float*)d_in[0];
    const float* W_ih0  = (const float*)d_in[1];
    const float* W_hh0  = (const float*)d_in[2];
    const float* b_ih0  = (const float*)d_in[3];
    const float* b_hh0  = (const float*)d_in[4];
    const float* W_ih1  = (const float*)d_in[5];
    const float* W_hh1  = (const float*)d_in[6];
    const float* b_ih1  = (const float*)d_in[7];
    const float* b_hh1  = (const float*)d_in[8];
    const float* W_cq   = (const float*)d_in[9];
    const float* b_cq   = (const float*)d_in[10];
    const float* mkeys  = (const float*)d_in[11];
    const float* mvals  = (const float*)d_in[12];
    const float* W_out  = (const float*)d_in[13];
    const float* b_out  = (const float*)d_in[14];
    const float* cw     = (const float*)d_in[15];
    const float* qw     = (const float*)d_in[16];
    float* out = (float*)d_out;

    float* mv = nullptr; cudaGetSymbolAddress((void**)&mv, g_mv);

    // #1 zero pipeline sync state (graph-replay safe)
    zero_sync_kernel<<<1, 128>>>();

    // #2 permute weights/biases + fp16 split of W_hh
    prep_kernel<<<G4, 256>>>(W_hh0, W_hh1, W_ih0, W_ih1,
                             b_ih0, b_hh0, b_ih1, b_hh1);
    // #3 MV = mem_vals @ Wq^T
    mv_kernel<<<MMEM, HSZ>>>(mvals, W_out, mv);

    // #4 fused pipeline: xg0 streamers + both scans + xg1 streamers
    fused_pipeline<<<96, 256>>>(x);

    // #5 fused tail: kNN + output GEMM, full chip
    tail_kernel<<<NTOK / 64, 256>>>(W_cq, b_cq, mkeys, qw,
                                    W_out, b_out, cw, out);
}